// round 4
// baseline (speedup 1.0000x reference)
#include <cuda_runtime.h>
#include <math.h>

// Problem constants
#define BB 2
#define SS 2048
#define DD 1024
#define HH 16
#define HDIM 64
#define MTOT (BB*SS)          // 4096

// Scratch (device globals: no allocation allowed)
__device__ float g_Q[BB*HH*SS*HDIM];   // [b,h,s,hd]
__device__ float g_K[BB*HH*SS*HDIM];
__device__ float g_V[BB*HH*SS*HDIM];
__device__ float g_X[BB*SS*DD];        // attention output, [b,s,d]
__device__ float g_MB[BB*SS];          // combined mask bias (0 or -inf)

// ---------------------------------------------------------------------------
// Combine key_padding_mask | attn_mask into an additive bias per (b, key).
// Robust to the masks arriving as int32 (likely: JAX bool -> int32) or uint8.
// Detection: scan bytes [0,4096) at offsets with (i & 3) != 0. For int32 0/1
// data those are all zero; for uint8 bool data they are random 0/1 bits and
// some are certainly nonzero. Only reads within the smaller possible buffer.
// Single block, 1024 threads.
// ---------------------------------------------------------------------------
__global__ void mask_kernel(const unsigned char* __restrict__ kpm,
                            const unsigned char* __restrict__ am,
                            float* __restrict__ mb) {
    __shared__ int nonaligned;
    if (threadIdx.x == 0) nonaligned = 0;
    __syncthreads();
    int hit = 0;
    for (int i = threadIdx.x; i < 4096; i += 1024) {
        if ((i & 3) != 0 && (kpm[i] | am[i])) hit = 1;
    }
    if (hit) nonaligned = 1;
    __syncthreads();
    bool is_u8 = (nonaligned != 0);
    for (int i = threadIdx.x; i < BB * SS; i += 1024) {
        unsigned char k, a;
        if (is_u8) { k = kpm[i];     a = am[i];     }
        else       { k = kpm[4 * i]; a = am[4 * i]; }   // low byte of int32 0/1
        mb[i] = (k | a) ? -INFINITY : 0.0f;
    }
}

// ---------------------------------------------------------------------------
// GEMM: out[m,n] = sum_k A[m,k] * W[n,k] + bias[n]
// A: [4096,1024] row-major; W: [1024,1024] row-major (torch Linear weight)
// headwise=1: write to [b,h,s,hd] layout (for Q/K/V); else flat [m,n].
// Tiles: BM=BN=64, BK=16; 256 threads; 4x4 per-thread microtile.
// ---------------------------------------------------------------------------
__global__ void gemm64(const float* __restrict__ A,
                       const float* __restrict__ W,
                       const float* __restrict__ bias,
                       float* __restrict__ out,
                       int headwise) {
    const int K = DD, N = DD;
    __shared__ float As[16][64];
    __shared__ float Bs[16][64];

    int tid = threadIdx.x;
    int tx = tid & 15;          // n-group
    int ty = tid >> 4;          // m-group
    int m0 = blockIdx.y * 64;
    int n0 = blockIdx.x * 64;

    int lr = tid >> 2;          // 0..63 row within tile
    int lq = tid & 3;           // 0..3 float4 chunk of BK=16

    const float* Aptr = A + (size_t)(m0 + lr) * K + lq * 4;
    const float* Wptr = W + (size_t)(n0 + lr) * K + lq * 4;

    float c[4][4] = {};

    for (int k0 = 0; k0 < K; k0 += 16) {
        float4 av = *(const float4*)(Aptr + k0);
        float4 bv = *(const float4*)(Wptr + k0);
        As[lq * 4 + 0][lr] = av.x;
        As[lq * 4 + 1][lr] = av.y;
        As[lq * 4 + 2][lr] = av.z;
        As[lq * 4 + 3][lr] = av.w;
        Bs[lq * 4 + 0][lr] = bv.x;
        Bs[lq * 4 + 1][lr] = bv.y;
        Bs[lq * 4 + 2][lr] = bv.z;
        Bs[lq * 4 + 3][lr] = bv.w;
        __syncthreads();

#pragma unroll
        for (int kk = 0; kk < 16; kk++) {
            float4 a = *(const float4*)&As[kk][ty * 4];
            float4 b = *(const float4*)&Bs[kk][tx * 4];
            c[0][0] += a.x * b.x; c[0][1] += a.x * b.y; c[0][2] += a.x * b.z; c[0][3] += a.x * b.w;
            c[1][0] += a.y * b.x; c[1][1] += a.y * b.y; c[1][2] += a.y * b.z; c[1][3] += a.y * b.w;
            c[2][0] += a.z * b.x; c[2][1] += a.z * b.y; c[2][2] += a.z * b.z; c[2][3] += a.z * b.w;
            c[3][0] += a.w * b.x; c[3][1] += a.w * b.y; c[3][2] += a.w * b.z; c[3][3] += a.w * b.w;
        }
        __syncthreads();
    }

#pragma unroll
    for (int i = 0; i < 4; i++) {
        int m = m0 + ty * 4 + i;
#pragma unroll
        for (int j = 0; j < 4; j++) {
            int n = n0 + tx * 4 + j;
            float val = c[i][j] + bias[n];
            if (headwise) {
                int b  = m >> 11;        // m / 2048
                int s  = m & 2047;
                int h  = n >> 6;         // n / 64
                int hd = n & 63;
                out[(((size_t)(b * HH + h)) * SS + s) * HDIM + hd] = val;
            } else {
                out[(size_t)m * N + n] = val;
            }
        }
    }
}

// ---------------------------------------------------------------------------
// Flash attention: per block = one (b,h) and a 64-query tile.
// Online softmax over 32 key tiles of 64. P reuses K's smem buffer.
// Dynamic smem: 3 * 64 * 65 floats = 49920 B.
// ---------------------------------------------------------------------------
__global__ void attn_kernel(const float* __restrict__ gQ,
                            const float* __restrict__ gK,
                            const float* __restrict__ gV,
                            const float* __restrict__ mb,
                            float* __restrict__ gX) {
    extern __shared__ float sm[];
    float* Qs  = sm;                  // [64][65]
    float* KPs = sm + 64 * 65;        // [64][65]  (K tile, then reused for P)
    float* Vs  = sm + 2 * 64 * 65;    // [64][65]

    const int tid = threadIdx.x;
    const int tx = tid & 15;          // key/hd column group
    const int ty = tid >> 4;          // query row group
    const int qt = blockIdx.x;        // query tile index (0..31)
    const int bh = blockIdx.y;        // b*H + h
    const int b  = bh >> 4;
    const int h  = bh & 15;

    const float* Qbase = gQ + ((size_t)bh * SS + qt * 64) * HDIM;
    const float* Kbase = gK + (size_t)bh * SS * HDIM;
    const float* Vbase = gV + (size_t)bh * SS * HDIM;
    const float* mbb   = mb + (size_t)b * SS;

    // Load Q tile [64][64] -> Qs stride 65
#pragma unroll
    for (int it = 0; it < 4; it++) {
        int e = it * 256 + tid;
        int r = e >> 4;
        int c4 = e & 15;
        float4 v = *(const float4*)(Qbase + r * HDIM + c4 * 4);
        float* d = &Qs[r * 65 + c4 * 4];
        d[0] = v.x; d[1] = v.y; d[2] = v.z; d[3] = v.w;
    }

    float m_i[4], l_i[4], o[4][4];
#pragma unroll
    for (int i = 0; i < 4; i++) {
        m_i[i] = -INFINITY;
        l_i[i] = 0.0f;
#pragma unroll
        for (int j = 0; j < 4; j++) o[i][j] = 0.0f;
    }

    const unsigned FULL = 0xffffffffu;

    for (int kt = 0; kt < 32; kt++) {
        __syncthreads();  // previous-iteration KPs/Vs readers done
        // Load K and V tiles
#pragma unroll
        for (int it = 0; it < 4; it++) {
            int e = it * 256 + tid;
            int r = e >> 4;
            int c4 = e & 15;
            size_t goff = ((size_t)(kt * 64 + r)) * HDIM + c4 * 4;
            float4 kv = *(const float4*)(Kbase + goff);
            float4 vv = *(const float4*)(Vbase + goff);
            float* dk = &KPs[r * 65 + c4 * 4];
            dk[0] = kv.x; dk[1] = kv.y; dk[2] = kv.z; dk[3] = kv.w;
            float* dv = &Vs[r * 65 + c4 * 4];
            dv[0] = vv.x; dv[1] = vv.y; dv[2] = vv.z; dv[3] = vv.w;
        }
        __syncthreads();

        // S = Q K^T
        float s[4][4] = {};
#pragma unroll 8
        for (int kk = 0; kk < 64; kk++) {
            float a0 = Qs[(ty * 4 + 0) * 65 + kk];
            float a1 = Qs[(ty * 4 + 1) * 65 + kk];
            float a2 = Qs[(ty * 4 + 2) * 65 + kk];
            float a3 = Qs[(ty * 4 + 3) * 65 + kk];
            float b0 = KPs[(tx * 4 + 0) * 65 + kk];
            float b1 = KPs[(tx * 4 + 1) * 65 + kk];
            float b2 = KPs[(tx * 4 + 2) * 65 + kk];
            float b3 = KPs[(tx * 4 + 3) * 65 + kk];
            s[0][0] += a0 * b0; s[0][1] += a0 * b1; s[0][2] += a0 * b2; s[0][3] += a0 * b3;
            s[1][0] += a1 * b0; s[1][1] += a1 * b1; s[1][2] += a1 * b2; s[1][3] += a1 * b3;
            s[2][0] += a2 * b0; s[2][1] += a2 * b1; s[2][2] += a2 * b2; s[2][3] += a2 * b3;
            s[3][0] += a3 * b0; s[3][1] += a3 * b1; s[3][2] += a3 * b2; s[3][3] += a3 * b3;
        }

        // scale + mask bias
        float mk[4];
#pragma unroll
        for (int j = 0; j < 4; j++) mk[j] = mbb[kt * 64 + tx * 4 + j];
#pragma unroll
        for (int i = 0; i < 4; i++)
#pragma unroll
            for (int j = 0; j < 4; j++)
                s[i][j] = s[i][j] * 0.125f + mk[j];

        // online softmax update
        float mnew[4], rs[4], fac[4];
#pragma unroll
        for (int i = 0; i < 4; i++) {
            float tm = fmaxf(fmaxf(s[i][0], s[i][1]), fmaxf(s[i][2], s[i][3]));
#pragma unroll
            for (int off = 8; off >= 1; off >>= 1)
                tm = fmaxf(tm, __shfl_xor_sync(FULL, tm, off, 16));
            mnew[i] = fmaxf(m_i[i], tm);
            bool dead = (mnew[i] == -INFINITY);
            float acc = 0.0f;
#pragma unroll
            for (int j = 0; j < 4; j++) {
                float p = dead ? 0.0f : __expf(s[i][j] - mnew[i]);
                s[i][j] = p;
                acc += p;
            }
#pragma unroll
            for (int off = 8; off >= 1; off >>= 1)
                acc += __shfl_xor_sync(FULL, acc, off, 16);
            rs[i] = acc;
            fac[i] = dead ? 1.0f : __expf(m_i[i] - mnew[i]);
            l_i[i] = l_i[i] * fac[i] + rs[i];
            m_i[i] = mnew[i];
        }
#pragma unroll
        for (int i = 0; i < 4; i++)
#pragma unroll
            for (int j = 0; j < 4; j++)
                o[i][j] *= fac[i];

        // write P into K's buffer
        __syncthreads();
#pragma unroll
        for (int i = 0; i < 4; i++)
#pragma unroll
            for (int j = 0; j < 4; j++)
                KPs[(ty * 4 + i) * 65 + tx * 4 + j] = s[i][j];
        __syncthreads();

        // O += P V
#pragma unroll 8
        for (int kk = 0; kk < 64; kk++) {
            float p0 = KPs[(ty * 4 + 0) * 65 + kk];
            float p1 = KPs[(ty * 4 + 1) * 65 + kk];
            float p2 = KPs[(ty * 4 + 2) * 65 + kk];
            float p3 = KPs[(ty * 4 + 3) * 65 + kk];
            float v0 = Vs[kk * 65 + tx * 4 + 0];
            float v1 = Vs[kk * 65 + tx * 4 + 1];
            float v2 = Vs[kk * 65 + tx * 4 + 2];
            float v3 = Vs[kk * 65 + tx * 4 + 3];
            o[0][0] += p0 * v0; o[0][1] += p0 * v1; o[0][2] += p0 * v2; o[0][3] += p0 * v3;
            o[1][0] += p1 * v0; o[1][1] += p1 * v1; o[1][2] += p1 * v2; o[1][3] += p1 * v3;
            o[2][0] += p2 * v0; o[2][1] += p2 * v1; o[2][2] += p2 * v2; o[2][3] += p2 * v3;
            o[3][0] += p3 * v0; o[3][1] += p3 * v1; o[3][2] += p3 * v2; o[3][3] += p3 * v3;
        }
    }

    // epilogue: normalize and write to g_X [b,s,d]
#pragma unroll
    for (int i = 0; i < 4; i++) {
        float rinv = (l_i[i] > 0.0f) ? (1.0f / l_i[i]) : 0.0f;
        int row = b * SS + qt * 64 + ty * 4 + i;
#pragma unroll
        for (int j = 0; j < 4; j++) {
            int col = h * HDIM + tx * 4 + j;
            gX[(size_t)row * DD + col] = o[i][j] * rinv;
        }
    }
}

// ---------------------------------------------------------------------------
// Launch
// ---------------------------------------------------------------------------
extern "C" void kernel_launch(void* const* d_in, const int* in_sizes, int n_in,
                              void* d_out, int out_size) {
    const float* query = (const float*)d_in[0];
    const float* key   = (const float*)d_in[1];
    const float* value = (const float*)d_in[2];
    const unsigned char* kpm = (const unsigned char*)d_in[3];
    const unsigned char* am  = (const unsigned char*)d_in[4];
    // d_in[5] = is_casual (ignored in eval mode)
    const float* Wq = (const float*)d_in[6];
    const float* bq = (const float*)d_in[7];
    const float* Wk = (const float*)d_in[8];
    const float* bk = (const float*)d_in[9];
    const float* Wv = (const float*)d_in[10];
    const float* bv = (const float*)d_in[11];
    const float* Wo = (const float*)d_in[12];
    const float* bo = (const float*)d_in[13];
    float* out = (float*)d_out;

    float *qptr, *kptr, *vptr, *xptr, *mbptr;
    cudaGetSymbolAddress((void**)&qptr, g_Q);
    cudaGetSymbolAddress((void**)&kptr, g_K);
    cudaGetSymbolAddress((void**)&vptr, g_V);
    cudaGetSymbolAddress((void**)&xptr, g_X);
    cudaGetSymbolAddress((void**)&mbptr, g_MB);

    const int ATTN_SMEM = 3 * 64 * 65 * sizeof(float);  // 49920 B
    cudaFuncSetAttribute(attn_kernel, cudaFuncAttributeMaxDynamicSharedMemorySize, ATTN_SMEM);

    mask_kernel<<<1, 1024>>>(kpm, am, mbptr);

    dim3 ggrid(DD / 64, MTOT / 64);   // (16, 64)
    gemm64<<<ggrid, 256>>>(query, Wq, bq, qptr, 1);
    gemm64<<<ggrid, 256>>>(key,   Wk, bk, kptr, 1);
    gemm64<<<ggrid, 256>>>(value, Wv, bv, vptr, 1);

    dim3 agrid(SS / 64, BB * HH);     // (32, 32)
    attn_kernel<<<agrid, 256, ATTN_SMEM>>>(qptr, kptr, vptr, mbptr, xptr);

    gemm64<<<ggrid, 256>>>(xptr, Wo, bo, out, 0);
}

// round 12
// speedup vs baseline: 2.7351x; 2.7351x over previous
#include <cuda_runtime.h>
#include <cuda_bf16.h>
#include <math.h>
#include <stdint.h>

#define BB 2
#define SS 2048
#define DD 1024
#define HH 16
#define HDIM 64
#define MTOT (BB*SS)          // 4096

// Scratch (device globals)
__device__ float g_MB[BB*SS];
__device__ __nv_bfloat16 g_A2[MTOT*3072];   // expanded activations [Ahi|Alo|Ahi]
__device__ __nv_bfloat16 g_W2[DD*3072];     // expanded weights     [Whi|Whi|Wlo]
__device__ __nv_bfloat16 g_Qh[MTOT*DD], g_Ql[MTOT*DD];   // [b,h,s,hd]
__device__ __nv_bfloat16 g_Kh[MTOT*DD], g_Kl[MTOT*DD];
__device__ __nv_bfloat16 g_Vh[MTOT*DD], g_Vl[MTOT*DD];

// ---------------------------------------------------------------------------
// helpers
// ---------------------------------------------------------------------------
__device__ __forceinline__ uint32_t s2u(const void* p) {
    uint32_t a;
    asm("{ .reg .u64 t; cvta.to.shared.u64 t, %1; cvt.u32.u64 %0, t; }" : "=r"(a) : "l"(p));
    return a;
}
__device__ __forceinline__ void ldm4(uint32_t* r, uint32_t addr) {
    asm volatile("ldmatrix.sync.aligned.m8n8.x4.shared.b16 {%0,%1,%2,%3}, [%4];"
        : "=r"(r[0]), "=r"(r[1]), "=r"(r[2]), "=r"(r[3]) : "r"(addr));
}
__device__ __forceinline__ void ldm4t(uint32_t* r, uint32_t addr) {
    asm volatile("ldmatrix.sync.aligned.m8n8.x4.trans.shared.b16 {%0,%1,%2,%3}, [%4];"
        : "=r"(r[0]), "=r"(r[1]), "=r"(r[2]), "=r"(r[3]) : "r"(addr));
}
__device__ __forceinline__ void mma_bf16(float* c, const uint32_t* a, uint32_t b0, uint32_t b1) {
    asm volatile("mma.sync.aligned.m16n8k16.row.col.f32.bf16.bf16.f32 "
        "{%0,%1,%2,%3}, {%4,%5,%6,%7}, {%8,%9}, {%0,%1,%2,%3};"
        : "+f"(c[0]), "+f"(c[1]), "+f"(c[2]), "+f"(c[3])
        : "r"(a[0]), "r"(a[1]), "r"(a[2]), "r"(a[3]), "r"(b0), "r"(b1));
}
__device__ __forceinline__ uint32_t packhi2(float x, float y, __nv_bfloat16& hx, __nv_bfloat16& hy) {
    hx = __float2bfloat16(x); hy = __float2bfloat16(y);
    __nv_bfloat162 t = __halves2bfloat162(hx, hy);
    return *(uint32_t*)&t;
}
__device__ __forceinline__ uint32_t packlo2(float x, float y, __nv_bfloat16 hx, __nv_bfloat16 hy) {
    __nv_bfloat162 t = __halves2bfloat162(
        __float2bfloat16(x - __bfloat162float(hx)),
        __float2bfloat16(y - __bfloat162float(hy)));
    return *(uint32_t*)&t;
}

// ---------------------------------------------------------------------------
// mask: robust to int32 or uint8 bool serialization
// ---------------------------------------------------------------------------
__global__ void mask_kernel(const unsigned char* __restrict__ kpm,
                            const unsigned char* __restrict__ am,
                            float* __restrict__ mb) {
    __shared__ int nonaligned;
    if (threadIdx.x == 0) nonaligned = 0;
    __syncthreads();
    int hit = 0;
    for (int i = threadIdx.x; i < 4096; i += 1024)
        if ((i & 3) != 0 && (kpm[i] | am[i])) hit = 1;
    if (hit) nonaligned = 1;
    __syncthreads();
    bool is_u8 = (nonaligned != 0);
    for (int i = threadIdx.x; i < BB * SS; i += 1024) {
        unsigned char k, a;
        if (is_u8) { k = kpm[i];     a = am[i];     }
        else       { k = kpm[4 * i]; a = am[4 * i]; }
        mb[i] = (k | a) ? -INFINITY : 0.0f;
    }
}

// ---------------------------------------------------------------------------
// fp32 -> expanded split-bf16 staging
// A2 row (3072): [hi | lo | hi];  W2 row (3072): [hi | hi | lo]
// ---------------------------------------------------------------------------
__global__ void conv_act(const float* __restrict__ in, __nv_bfloat16* __restrict__ A2) {
    int i = blockIdx.x * 256 + threadIdx.x;   // one float4 each; grid sized exactly
    float4 v = ((const float4*)in)[i];
    int m = i >> 8, c4 = i & 255;             // col = c4*4
    __nv_bfloat162* O = (__nv_bfloat162*)A2;
    size_t base = (size_t)m * 1536 + c4 * 2;
    __nv_bfloat16 h0, h1, h2, h3;
    uint32_t hiA = packhi2(v.x, v.y, h0, h1);
    uint32_t hiB = packhi2(v.z, v.w, h2, h3);
    uint32_t loA = packlo2(v.x, v.y, h0, h1);
    uint32_t loB = packlo2(v.z, v.w, h2, h3);
    O[base]        = *(__nv_bfloat162*)&hiA;  O[base + 1]    = *(__nv_bfloat162*)&hiB;
    O[base + 1024] = *(__nv_bfloat162*)&hiA;  O[base + 1025] = *(__nv_bfloat162*)&hiB;
    O[base + 512]  = *(__nv_bfloat162*)&loA;  O[base + 513]  = *(__nv_bfloat162*)&loB;
}
__global__ void conv_wgt(const float* __restrict__ in, __nv_bfloat16* __restrict__ W2) {
    int i = blockIdx.x * 256 + threadIdx.x;
    float4 v = ((const float4*)in)[i];
    int n = i >> 8, c4 = i & 255;
    __nv_bfloat162* O = (__nv_bfloat162*)W2;
    size_t base = (size_t)n * 1536 + c4 * 2;
    __nv_bfloat16 h0, h1, h2, h3;
    uint32_t hiA = packhi2(v.x, v.y, h0, h1);
    uint32_t hiB = packhi2(v.z, v.w, h2, h3);
    uint32_t loA = packlo2(v.x, v.y, h0, h1);
    uint32_t loB = packlo2(v.z, v.w, h2, h3);
    O[base]        = *(__nv_bfloat162*)&hiA;  O[base + 1]    = *(__nv_bfloat162*)&hiB;
    O[base + 512]  = *(__nv_bfloat162*)&hiA;  O[base + 513]  = *(__nv_bfloat162*)&hiB;
    O[base + 1024] = *(__nv_bfloat162*)&loA;  O[base + 1025] = *(__nv_bfloat162*)&loB;
}

// ---------------------------------------------------------------------------
// GEMM via mma.sync: C[m,n] = sum_{k<3072} A2[m,k]*W2[n,k]  (+bias)
// block 128x128, 8 warps (4m x 2n), warp tile 32x64. K-chunks of 64, reg-pipelined.
// mode 0: out[m][1024] fp32   mode 1: headwise bf16 hi/lo split (Q/K/V)
// ---------------------------------------------------------------------------
#define SAS 72
__global__ void __launch_bounds__(256, 1)
gemm_mma(const __nv_bfloat16* __restrict__ A2, const __nv_bfloat16* __restrict__ W2,
         const float* __restrict__ bias, float* __restrict__ out,
         __nv_bfloat16* __restrict__ Oh, __nv_bfloat16* __restrict__ Ol, int mode)
{
    __shared__ __nv_bfloat16 sA[128 * SAS];
    __shared__ __nv_bfloat16 sB[128 * SAS];
    const int tid = threadIdx.x;
    const int lane = tid & 31;
    const int wid = tid >> 5;
    const int wm = wid & 3, wn = wid >> 2;
    const int m0 = blockIdx.y * 128, n0 = blockIdx.x * 128;
    const uint32_t sAu = s2u(sA), sBu = s2u(sB);

    const uint4* A4 = (const uint4*)A2;   // row stride 384 uint4
    const uint4* W4 = (const uint4*)W2;

    uint4 pa[4], pb[4];
#pragma unroll
    for (int it = 0; it < 4; it++) {
        int e = it * 256 + tid, r = e >> 3, c = e & 7;
        pa[it] = A4[(size_t)(m0 + r) * 384 + c];
        pb[it] = W4[(size_t)(n0 + r) * 384 + c];
    }

    float acc[2][8][4] = {};

    for (int ck = 0; ck < 48; ck++) {
        __syncthreads();
#pragma unroll
        for (int it = 0; it < 4; it++) {
            int e = it * 256 + tid, r = e >> 3, c = e & 7;
            *(uint4*)&sA[r * SAS + c * 8] = pa[it];
            *(uint4*)&sB[r * SAS + c * 8] = pb[it];
        }
        __syncthreads();
        if (ck < 47) {
#pragma unroll
            for (int it = 0; it < 4; it++) {
                int e = it * 256 + tid, r = e >> 3, c = e & 7;
                pa[it] = A4[(size_t)(m0 + r) * 384 + (ck + 1) * 8 + c];
                pb[it] = W4[(size_t)(n0 + r) * 384 + (ck + 1) * 8 + c];
            }
        }
        const int arow = (lane & 7) + ((lane >> 3) & 1) * 8;
        const int brow = (lane & 7) + (lane >> 4) * 8;
#pragma unroll
        for (int ks = 0; ks < 4; ks++) {
            const int k0 = ks * 16;
            const int acol = k0 + (lane >> 4) * 8;
            const int bcol = k0 + ((lane >> 3) & 1) * 8;
            uint32_t a[2][4];
#pragma unroll
            for (int i = 0; i < 2; i++)
                ldm4(a[i], sAu + ((wm * 32 + i * 16 + arow) * SAS + acol) * 2);
            uint32_t bf[4][4];
#pragma unroll
            for (int j = 0; j < 4; j++)
                ldm4(bf[j], sBu + ((wn * 64 + j * 16 + brow) * SAS + bcol) * 2);
#pragma unroll
            for (int i = 0; i < 2; i++)
#pragma unroll
                for (int jj = 0; jj < 8; jj++)
                    mma_bf16(acc[i][jj], a[i], bf[jj >> 1][(jj & 1) * 2], bf[jj >> 1][(jj & 1) * 2 + 1]);
        }
    }

    // epilogue
    const int q = lane & 3, r4 = lane >> 2;
#pragma unroll
    for (int i = 0; i < 2; i++) {
        int mbase = m0 + wm * 32 + i * 16 + r4;
#pragma unroll
        for (int jj = 0; jj < 8; jj++) {
            int n = n0 + wn * 64 + jj * 8 + q * 2;
            float b0v = bias[n], b1v = bias[n + 1];
#pragma unroll
            for (int half = 0; half < 2; half++) {
                int m = mbase + half * 8;
                float v0 = acc[i][jj][half * 2 + 0] + b0v;
                float v1 = acc[i][jj][half * 2 + 1] + b1v;
                if (mode == 0) {
                    out[(size_t)m * DD + n]     = v0;
                    out[(size_t)m * DD + n + 1] = v1;
                } else {
                    int b = m >> 11, s = m & 2047, h = n >> 6, hd = n & 63;
                    size_t idx = (((size_t)(b * HH + h)) * SS + s) * HDIM + hd;
                    __nv_bfloat16 h0, h1;
                    uint32_t hi = packhi2(v0, v1, h0, h1);
                    uint32_t lo = packlo2(v0, v1, h0, h1);
                    *(__nv_bfloat162*)&Oh[idx] = *(__nv_bfloat162*)&hi;
                    *(__nv_bfloat162*)&Ol[idx] = *(__nv_bfloat162*)&lo;
                }
            }
        }
    }
}

// ---------------------------------------------------------------------------
// Flash attention via mma.sync (split-bf16, 3-term both GEMMs)
// block = 128 threads (4 warps), q-tile 64 (warp = 16 rows x 64 cols)
// Writes output directly into expanded A2 staging ([hi|lo|hi]).
// ---------------------------------------------------------------------------
#define VST 72
__global__ void __launch_bounds__(128, 2)
attn_mma(const __nv_bfloat16* __restrict__ Qh, const __nv_bfloat16* __restrict__ Ql,
         const __nv_bfloat16* __restrict__ Kh, const __nv_bfloat16* __restrict__ Kl,
         const __nv_bfloat16* __restrict__ Vh, const __nv_bfloat16* __restrict__ Vl,
         const float* __restrict__ mb, __nv_bfloat16* __restrict__ A2out)
{
    extern __shared__ __nv_bfloat16 smb[];
    __nv_bfloat16* sQh = smb;                 // [64][VST] each
    __nv_bfloat16* sQl = smb + 64 * VST;
    __nv_bfloat16* sKh = smb + 2 * 64 * VST;
    __nv_bfloat16* sKl = smb + 3 * 64 * VST;
    __nv_bfloat16* sVh = smb + 4 * 64 * VST;
    __nv_bfloat16* sVl = smb + 5 * 64 * VST;

    const int tid = threadIdx.x, lane = tid & 31, wq = tid >> 5;
    const int qt = blockIdx.x, bh = blockIdx.y;
    const int b = bh >> 4, h = bh & 15;
    const float* mbb = mb + b * SS;

    const uint4* Qh4 = (const uint4*)(Qh + ((size_t)bh * SS + qt * 64) * HDIM);
    const uint4* Ql4 = (const uint4*)(Ql + ((size_t)bh * SS + qt * 64) * HDIM);
    const uint4* Kh4 = (const uint4*)(Kh + (size_t)bh * SS * HDIM);
    const uint4* Kl4 = (const uint4*)(Kl + (size_t)bh * SS * HDIM);
    const uint4* Vh4 = (const uint4*)(Vh + (size_t)bh * SS * HDIM);
    const uint4* Vl4 = (const uint4*)(Vl + (size_t)bh * SS * HDIM);

#pragma unroll
    for (int it = 0; it < 4; it++) {
        int e = it * 128 + tid, r = e >> 3, c = e & 7;
        *(uint4*)&sQh[r * VST + c * 8] = Qh4[r * 8 + c];
        *(uint4*)&sQl[r * VST + c * 8] = Ql4[r * 8 + c];
    }

    const uint32_t sQhu = s2u(sQh), sQlu = s2u(sQl);
    const uint32_t sKhu = s2u(sKh), sKlu = s2u(sKl);
    const uint32_t sVhu = s2u(sVh), sVlu = s2u(sVl);

    float oacc[8][4] = {};
    float m0r = -INFINITY, m1r = -INFINITY, l0r = 0.0f, l1r = 0.0f;
    const int q = lane & 3;
    const unsigned FULL = 0xffffffffu;

    for (int kt = 0; kt < 32; kt++) {
        __syncthreads();
#pragma unroll
        for (int it = 0; it < 4; it++) {
            int e = it * 128 + tid, r = e >> 3, c = e & 7;
            int gr = kt * 64 + r;
            *(uint4*)&sKh[r * VST + c * 8] = Kh4[gr * 8 + c];
            *(uint4*)&sKl[r * VST + c * 8] = Kl4[gr * 8 + c];
            *(uint4*)&sVh[r * VST + c * 8] = Vh4[gr * 8 + c];
            *(uint4*)&sVl[r * VST + c * 8] = Vl4[gr * 8 + c];
        }
        __syncthreads();

        // ---- S = Q K^T (3-term split) ----
        float p[8][4] = {};
        const int arow = (lane & 7) + ((lane >> 3) & 1) * 8;
        const int brow = (lane & 7) + (lane >> 4) * 8;
#pragma unroll
        for (int ks = 0; ks < 4; ks++) {
            const int k0 = ks * 16;
            const int acol = k0 + (lane >> 4) * 8;
            const int bcol = k0 + ((lane >> 3) & 1) * 8;
            uint32_t qhf[4], qlf[4];
            ldm4(qhf, sQhu + ((wq * 16 + arow) * VST + acol) * 2);
            ldm4(qlf, sQlu + ((wq * 16 + arow) * VST + acol) * 2);
#pragma unroll
            for (int j = 0; j < 4; j++) {
                uint32_t khf[4], klf[4];
                ldm4(khf, sKhu + ((j * 16 + brow) * VST + bcol) * 2);
                ldm4(klf, sKlu + ((j * 16 + brow) * VST + bcol) * 2);
#pragma unroll
                for (int jj = 0; jj < 2; jj++) {
                    float* cc = p[j * 2 + jj];
                    mma_bf16(cc, qhf, khf[jj * 2], khf[jj * 2 + 1]);
                    mma_bf16(cc, qlf, khf[jj * 2], khf[jj * 2 + 1]);
                    mma_bf16(cc, qhf, klf[jj * 2], klf[jj * 2 + 1]);
                }
            }
        }

        // ---- softmax (online) ----
        float mx0 = -INFINITY, mx1 = -INFINITY;
#pragma unroll
        for (int jj = 0; jj < 8; jj++) {
            float mk0 = mbb[kt * 64 + jj * 8 + q * 2];
            float mk1 = mbb[kt * 64 + jj * 8 + q * 2 + 1];
            p[jj][0] = p[jj][0] * 0.125f + mk0;
            p[jj][1] = p[jj][1] * 0.125f + mk1;
            p[jj][2] = p[jj][2] * 0.125f + mk0;
            p[jj][3] = p[jj][3] * 0.125f + mk1;
            mx0 = fmaxf(mx0, fmaxf(p[jj][0], p[jj][1]));
            mx1 = fmaxf(mx1, fmaxf(p[jj][2], p[jj][3]));
        }
        mx0 = fmaxf(mx0, __shfl_xor_sync(FULL, mx0, 1));
        mx0 = fmaxf(mx0, __shfl_xor_sync(FULL, mx0, 2));
        mx1 = fmaxf(mx1, __shfl_xor_sync(FULL, mx1, 1));
        mx1 = fmaxf(mx1, __shfl_xor_sync(FULL, mx1, 2));
        float mn0 = fmaxf(m0r, mx0), mn1 = fmaxf(m1r, mx1);
        bool d0 = (mn0 == -INFINITY), d1 = (mn1 == -INFINITY);
        float s0 = 0.0f, s1 = 0.0f;
#pragma unroll
        for (int jj = 0; jj < 8; jj++) {
            p[jj][0] = d0 ? 0.0f : __expf(p[jj][0] - mn0);
            p[jj][1] = d0 ? 0.0f : __expf(p[jj][1] - mn0);
            p[jj][2] = d1 ? 0.0f : __expf(p[jj][2] - mn1);
            p[jj][3] = d1 ? 0.0f : __expf(p[jj][3] - mn1);
            s0 += p[jj][0] + p[jj][1];
            s1 += p[jj][2] + p[jj][3];
        }
        s0 += __shfl_xor_sync(FULL, s0, 1);
        s0 += __shfl_xor_sync(FULL, s0, 2);
        s1 += __shfl_xor_sync(FULL, s1, 1);
        s1 += __shfl_xor_sync(FULL, s1, 2);
        float f0 = d0 ? 1.0f : __expf(m0r - mn0);
        float f1 = d1 ? 1.0f : __expf(m1r - mn1);
        l0r = l0r * f0 + s0;  l1r = l1r * f1 + s1;
        m0r = mn0;  m1r = mn1;
#pragma unroll
        for (int jj = 0; jj < 8; jj++) {
            oacc[jj][0] *= f0; oacc[jj][1] *= f0;
            oacc[jj][2] *= f1; oacc[jj][3] *= f1;
        }

        // ---- O += P V (3-term split; P-frags built in registers) ----
#pragma unroll
        for (int kk = 0; kk < 4; kk++) {
            uint32_t aPh[4], aPl[4];
#pragma unroll
            for (int u = 0; u < 2; u++) {
                float* pp = p[kk * 2 + u];
                __nv_bfloat16 h0, h1, h2, h3;
                aPh[u * 2 + 0] = packhi2(pp[0], pp[1], h0, h1);
                aPh[u * 2 + 1] = packhi2(pp[2], pp[3], h2, h3);
                aPl[u * 2 + 0] = packlo2(pp[0], pp[1], h0, h1);
                aPl[u * 2 + 1] = packlo2(pp[2], pp[3], h2, h3);
            }
            const int vrow = kk * 16 + (lane & 7) + ((lane >> 3) & 1) * 8;
            const int vcol = (lane >> 4) * 8;
#pragma unroll
            for (int j = 0; j < 4; j++) {
                uint32_t vhf[4], vlf[4];
                ldm4t(vhf, sVhu + (vrow * VST + j * 16 + vcol) * 2);
                ldm4t(vlf, sVlu + (vrow * VST + j * 16 + vcol) * 2);
#pragma unroll
                for (int jj = 0; jj < 2; jj++) {
                    float* cc = oacc[j * 2 + jj];
                    mma_bf16(cc, aPh, vhf[jj * 2], vhf[jj * 2 + 1]);
                    mma_bf16(cc, aPl, vhf[jj * 2], vhf[jj * 2 + 1]);
                    mma_bf16(cc, aPh, vlf[jj * 2], vlf[jj * 2 + 1]);
                }
            }
        }
    }

    // ---- epilogue: normalize, split, write into expanded A2 staging ----
    float rinv0 = (l0r > 0.0f) ? (1.0f / l0r) : 0.0f;
    float rinv1 = (l1r > 0.0f) ? (1.0f / l1r) : 0.0f;
    const int r4 = lane >> 2;
    const int s0row = qt * 64 + wq * 16 + r4;
    __nv_bfloat162* A22 = (__nv_bfloat162*)A2out;
#pragma unroll
    for (int jj = 0; jj < 8; jj++) {
        int col = h * HDIM + jj * 8 + q * 2;
#pragma unroll
        for (int half = 0; half < 2; half++) {
            int srow = s0row + half * 8;
            size_t m = (size_t)b * SS + srow;
            float sc = half ? rinv1 : rinv0;
            float v0 = oacc[jj][half * 2 + 0] * sc;
            float v1 = oacc[jj][half * 2 + 1] * sc;
            __nv_bfloat16 h0, h1;
            uint32_t hi = packhi2(v0, v1, h0, h1);
            uint32_t lo = packlo2(v0, v1, h0, h1);
            A22[m * 1536 + (col >> 1)]        = *(__nv_bfloat162*)&hi;
            A22[m * 1536 + 1024 + (col >> 1)] = *(__nv_bfloat162*)&hi;
            A22[m * 1536 + 512 + (col >> 1)]  = *(__nv_bfloat162*)&lo;
        }
    }
}

// ---------------------------------------------------------------------------
// Launch
// ---------------------------------------------------------------------------
extern "C" void kernel_launch(void* const* d_in, const int* in_sizes, int n_in,
                              void* d_out, int out_size) {
    const float* query = (const float*)d_in[0];
    const float* key   = (const float*)d_in[1];
    const float* value = (const float*)d_in[2];
    const unsigned char* kpm = (const unsigned char*)d_in[3];
    const unsigned char* am  = (const unsigned char*)d_in[4];
    // d_in[5] = is_casual (eval: unused)
    const float* Wq = (const float*)d_in[6];
    const float* bq = (const float*)d_in[7];
    const float* Wk = (const float*)d_in[8];
    const float* bk = (const float*)d_in[9];
    const float* Wv = (const float*)d_in[10];
    const float* bv = (const float*)d_in[11];
    const float* Wo = (const float*)d_in[12];
    const float* bo = (const float*)d_in[13];
    float* out = (float*)d_out;

    float* mbptr;
    __nv_bfloat16 *a2, *w2, *qh, *ql, *kh, *kl, *vh, *vl;
    cudaGetSymbolAddress((void**)&mbptr, g_MB);
    cudaGetSymbolAddress((void**)&a2, g_A2);
    cudaGetSymbolAddress((void**)&w2, g_W2);
    cudaGetSymbolAddress((void**)&qh, g_Qh);
    cudaGetSymbolAddress((void**)&ql, g_Ql);
    cudaGetSymbolAddress((void**)&kh, g_Kh);
    cudaGetSymbolAddress((void**)&kl, g_Kl);
    cudaGetSymbolAddress((void**)&vh, g_Vh);
    cudaGetSymbolAddress((void**)&vl, g_Vl);

    const int ATTN_SMEM = 6 * 64 * VST * sizeof(__nv_bfloat16);   // 55296 B
    cudaFuncSetAttribute(attn_mma, cudaFuncAttributeMaxDynamicSharedMemorySize, ATTN_SMEM);

    mask_kernel<<<1, 1024>>>(kpm, am, mbptr);

    dim3 ggrid(DD / 128, MTOT / 128);    // (8, 32)

    conv_act<<<MTOT * DD / 4 / 256, 256>>>(query, a2);
    conv_wgt<<<DD * DD / 4 / 256, 256>>>(Wq, w2);
    gemm_mma<<<ggrid, 256>>>(a2, w2, bq, nullptr, qh, ql, 1);

    conv_act<<<MTOT * DD / 4 / 256, 256>>>(key, a2);
    conv_wgt<<<DD * DD / 4 / 256, 256>>>(Wk, w2);
    gemm_mma<<<ggrid, 256>>>(a2, w2, bk, nullptr, kh, kl, 1);

    conv_act<<<MTOT * DD / 4 / 256, 256>>>(value, a2);
    conv_wgt<<<DD * DD / 4 / 256, 256>>>(Wv, w2);
    gemm_mma<<<ggrid, 256>>>(a2, w2, bv, nullptr, vh, vl, 1);

    dim3 agrid(SS / 64, BB * HH);        // (32, 32)
    attn_mma<<<agrid, 128, ATTN_SMEM>>>(qh, ql, kh, kl, vh, vl, mbptr, a2);

    conv_wgt<<<DD * DD / 4 / 256, 256>>>(Wo, w2);
    gemm_mma<<<ggrid, 256>>>(a2, w2, bo, out, nullptr, nullptr, 0);
}